// round 6
// baseline (speedup 1.0000x reference)
#include <cuda_runtime.h>
#include <cuda_bf16.h>

// FAPE loss, fused single kernel. B=4, N=2048.
//   d(i,j) = Rp_i^T xp_j + (-Rt_i^T) xt_j + dt_i,  dt_i = Rt_i^T tt_i - Rp_i^T tp_i
//   out[b] = 0.1 * mean_ij min(sqrt(||d||^2 + 1e-4), 10)
//
// R5: clean occupancy test. R1 inner loop (plain LDS.64 -> fma.rn.f32x2,
// 64 regs) + R4 coalesced frame staging + grid 512 + launch_bounds(256,4)
// (<=64 regs -> 4 blocks/SM possible, ~2x resident warps vs R4).

#define BB 4
#define NN 2048
#define NBI 8           // i-blocks of 256
#define NBJ 16          // j-chunks of 128
#define JCH 128
#define BLK 256
#define NBLOCKS (BB * NBI * NBJ)   // 512

__device__ float g_partials[NBLOCKS];
__device__ unsigned int g_count = 0;

typedef unsigned long long u64;

__device__ __forceinline__ u64 pack2(float x, float y) {
    u64 r; asm("mov.b64 %0, {%1,%2};" : "=l"(r) : "f"(x), "f"(y)); return r;
}
__device__ __forceinline__ void unpack2(u64 v, float& x, float& y) {
    asm("mov.b64 {%0,%1}, %2;" : "=f"(x), "=f"(y) : "l"(v));
}
__device__ __forceinline__ u64 ffma2(u64 a, u64 b, u64 c) {
    u64 d; asm("fma.rn.f32x2 %0, %1, %2, %3;" : "=l"(d) : "l"(a), "l"(b), "l"(c)); return d;
}
__device__ __forceinline__ float fsqrt_approx(float x) {
    float y; asm("sqrt.approx.f32 %0, %1;" : "=f"(y) : "f"(x)); return y;
}

__global__ void __launch_bounds__(BLK, 4)
fape_fused(const float* __restrict__ pR, const float* __restrict__ pT,
           const float* __restrict__ pX, const float* __restrict__ tR,
           const float* __restrict__ tT, const float* __restrict__ tX,
           float* __restrict__ out) {
    __shared__ __align__(8) float sy[6][JCH];    // SoA j-data: xp0..2, xt0..2
    __shared__ float sRp[BLK * 9];
    __shared__ float sRt[BLK * 9];
    __shared__ float sTp[BLK * 3];
    __shared__ float sTt[BLK * 3];
    __shared__ float swred[BLK / 32];

    const int bid = blockIdx.x;
    const int b  = bid >> 7;            // / (NBI*NBJ) = /128
    const int ib = (bid >> 4) & 7;
    const int jb = bid & 15;
    const int t  = threadIdx.x;

    // ---- Coalesced staging of this block's frames + j-chunk ----
    {
        const float* baseRp = pR + (b * NN + ib * BLK) * 9;
        const float* baseRt = tR + (b * NN + ib * BLK) * 9;
        const float* baseTp = pT + (b * NN + ib * BLK) * 3;
        const float* baseTt = tT + (b * NN + ib * BLK) * 3;
#pragma unroll
        for (int k = t; k < BLK * 9; k += BLK) { sRp[k] = baseRp[k]; sRt[k] = baseRt[k]; }
#pragma unroll
        for (int k = t; k < BLK * 3; k += BLK) { sTp[k] = baseTp[k]; sTt[k] = baseTt[k]; }

        if (t < JCH) {
            const int j = jb * JCH + t;
            const float* xp = pX + (b * NN + j) * 3;
            const float* xt = tX + (b * NN + j) * 3;
            sy[0][t] = xp[0]; sy[1][t] = xp[1]; sy[2][t] = xp[2];
            sy[3][t] = xt[0]; sy[4][t] = xt[1]; sy[5][t] = xt[2];
        }
    }
    __syncthreads();

    // ---- Build this thread's packed i-frame from shared ----
    u64 P[9], Q[9], DT[3];
    {
        const float* Rp = sRp + t * 9;
        const float* Rt = sRt + t * 9;
        const float tp0 = sTp[t*3+0], tp1 = sTp[t*3+1], tp2 = sTp[t*3+2];
        const float tt0 = sTt[t*3+0], tt1 = sTt[t*3+1], tt2 = sTt[t*3+2];
#pragma unroll
        for (int o = 0; o < 3; o++) {
            const float rp0 = Rp[0*3+o], rp1 = Rp[1*3+o], rp2 = Rp[2*3+o];
            const float rt0 = Rt[0*3+o], rt1 = Rt[1*3+o], rt2 = Rt[2*3+o];
            P[o*3+0] = pack2(rp0, rp0);
            P[o*3+1] = pack2(rp1, rp1);
            P[o*3+2] = pack2(rp2, rp2);
            Q[o*3+0] = pack2(-rt0, -rt0);
            Q[o*3+1] = pack2(-rt1, -rt1);
            Q[o*3+2] = pack2(-rt2, -rt2);
            const float dt = (rt0*tt0 + rt1*tt1 + rt2*tt2)
                           - (rp0*tp0 + rp1*tp1 + rp2*tp2);
            DT[o] = pack2(dt, dt);
        }
    }
    const u64 EPS2 = pack2(1e-4f, 1e-4f);

    float acc0 = 0.f, acc1 = 0.f;
#pragma unroll 4
    for (int j = 0; j < JCH; j += 2) {
        // Warp-uniform LDS.64: packed pair {y_j, y_{j+1}} per component.
        const u64 y0 = *(const u64*)&sy[0][j];
        const u64 y1 = *(const u64*)&sy[1][j];
        const u64 y2 = *(const u64*)&sy[2][j];
        const u64 y3 = *(const u64*)&sy[3][j];
        const u64 y4 = *(const u64*)&sy[4][j];
        const u64 y5 = *(const u64*)&sy[5][j];

        u64 d0 = ffma2(P[0], y0, ffma2(P[1], y1, ffma2(P[2], y2,
                 ffma2(Q[0], y3, ffma2(Q[1], y4, ffma2(Q[2], y5, DT[0]))))));
        u64 d1 = ffma2(P[3], y0, ffma2(P[4], y1, ffma2(P[5], y2,
                 ffma2(Q[3], y3, ffma2(Q[4], y4, ffma2(Q[5], y5, DT[1]))))));
        u64 d2 = ffma2(P[6], y0, ffma2(P[7], y1, ffma2(P[8], y2,
                 ffma2(Q[6], y3, ffma2(Q[7], y4, ffma2(Q[8], y5, DT[2]))))));

        u64 s2 = ffma2(d0, d0, ffma2(d1, d1, ffma2(d2, d2, EPS2)));
        float lo, hi;
        unpack2(s2, lo, hi);
        // min(sqrt(x+eps), 10) == sqrt(min(x+eps, 100))
        acc0 += fsqrt_approx(fminf(lo, 100.0f));
        acc1 += fsqrt_approx(fminf(hi, 100.0f));
    }

    // ---- Deterministic reduction: warp butterfly + cross-warp ----
    float v = acc0 + acc1;
#pragma unroll
    for (int m = 16; m >= 1; m >>= 1)
        v += __shfl_xor_sync(0xffffffffu, v, m);
    if ((t & 31) == 0) swred[t >> 5] = v;
    __syncthreads();
    if (t < 32) {
        float w = (t < BLK / 32) ? swred[t] : 0.f;
#pragma unroll
        for (int m = 4; m >= 1; m >>= 1)
            w += __shfl_xor_sync(0xffffffffu, w, m);
        if (t == 0) {
            g_partials[bid] = w;
            __threadfence();
            const unsigned r = atomicAdd(&g_count, 1);
            if (r == NBLOCKS - 1) {
                // Last block: fixed-order final sum (deterministic).
#pragma unroll
                for (int bb = 0; bb < BB; bb++) {
                    float s = 0.f;
                    for (int k = 0; k < NBI * NBJ; k++)
                        s += __ldcg(&g_partials[bb * (NBI * NBJ) + k]);
                    out[bb] = s * (1.0f / (10.0f * (float)NN * (float)NN));
                }
                g_count = 0;   // reset for next graph replay
            }
        }
    }
}

extern "C" void kernel_launch(void* const* d_in, const int* in_sizes, int n_in,
                              void* d_out, int out_size) {
    const float* pR = (const float*)d_in[0];  // predicted_rotations   [B,N,3,3]
    const float* pT = (const float*)d_in[1];  // predicted_translations[B,N,3]
    const float* pX = (const float*)d_in[2];  // predicted_atom_positions
    const float* tR = (const float*)d_in[3];  // true_rotations
    const float* tT = (const float*)d_in[4];  // true_translations
    const float* tX = (const float*)d_in[5];  // true_atom_positions

    fape_fused<<<NBLOCKS, BLK>>>(pR, pT, pX, tR, tT, tX, (float*)d_out);
}

// round 7
// speedup vs baseline: 1.0590x; 1.0590x over previous
#include <cuda_runtime.h>
#include <cuda_bf16.h>

// FAPE loss, fused single kernel. B=4, N=2048.
//   d(i,j) = Rp_i^T xp_j + (-Rt_i^T) xt_j + dt_i,  dt_i = Rt_i^T tt_i - Rp_i^T tp_i
//   out[b] = 0.1 * mean_ij min(sqrt(||d||^2 + 1e-4), 10)
//
// R6: 2-i register tiling. Each thread owns TWO i-frames; the 6 shared
// j-loads per iteration feed both -> LDS traffic per pair halves and the
// number of independent FFMA2 chains per warp doubles (covers the L1tex
// queue latency that pinned issue at ~52% across occ 17-30%).

#define BB 4
#define NN 2048
#define IBL 512         // i's per block (2 per thread)
#define NBI 4           // 2048/512
#define NBJ 16          // j-chunks of 128
#define JCH 128
#define BLK 256
#define NBLOCKS (BB * NBI * NBJ)   // 256

__device__ float g_partials[NBLOCKS];
__device__ unsigned int g_count = 0;

typedef unsigned long long u64;

__device__ __forceinline__ u64 pack2(float x, float y) {
    u64 r; asm("mov.b64 %0, {%1,%2};" : "=l"(r) : "f"(x), "f"(y)); return r;
}
__device__ __forceinline__ void unpack2(u64 v, float& x, float& y) {
    asm("mov.b64 {%0,%1}, %2;" : "=f"(x), "=f"(y) : "l"(v));
}
__device__ __forceinline__ u64 ffma2(u64 a, u64 b, u64 c) {
    u64 d; asm("fma.rn.f32x2 %0, %1, %2, %3;" : "=l"(d) : "l"(a), "l"(b), "l"(c)); return d;
}
__device__ __forceinline__ float fsqrt_approx(float x) {
    float y; asm("sqrt.approx.f32 %0, %1;" : "=f"(y) : "f"(x)); return y;
}

// Build one packed i-frame from staged shared arrays.
__device__ __forceinline__ void build_frame(
    const float* __restrict__ Rp, const float* __restrict__ Rt,
    const float* __restrict__ Tp, const float* __restrict__ Tt,
    u64* P, u64* Q, u64* DT)
{
    const float tp0 = Tp[0], tp1 = Tp[1], tp2 = Tp[2];
    const float tt0 = Tt[0], tt1 = Tt[1], tt2 = Tt[2];
#pragma unroll
    for (int o = 0; o < 3; o++) {
        const float rp0 = Rp[0*3+o], rp1 = Rp[1*3+o], rp2 = Rp[2*3+o];
        const float rt0 = Rt[0*3+o], rt1 = Rt[1*3+o], rt2 = Rt[2*3+o];
        P[o*3+0] = pack2(rp0, rp0);
        P[o*3+1] = pack2(rp1, rp1);
        P[o*3+2] = pack2(rp2, rp2);
        Q[o*3+0] = pack2(-rt0, -rt0);
        Q[o*3+1] = pack2(-rt1, -rt1);
        Q[o*3+2] = pack2(-rt2, -rt2);
        const float dt = (rt0*tt0 + rt1*tt1 + rt2*tt2)
                       - (rp0*tp0 + rp1*tp1 + rp2*tp2);
        DT[o] = pack2(dt, dt);
    }
}

__global__ void __launch_bounds__(BLK, 2)
fape_fused(const float* __restrict__ pR, const float* __restrict__ pT,
           const float* __restrict__ pX, const float* __restrict__ tR,
           const float* __restrict__ tT, const float* __restrict__ tX,
           float* __restrict__ out) {
    __shared__ __align__(8) float sy[6][JCH];    // SoA j-data
    __shared__ float sRp[IBL * 9];
    __shared__ float sRt[IBL * 9];
    __shared__ float sTp[IBL * 3];
    __shared__ float sTt[IBL * 3];
    __shared__ float swred[BLK / 32];

    const int bid = blockIdx.x;
    const int b  = bid >> 6;            // / (NBI*NBJ) = /64
    const int ib = (bid >> 4) & 3;
    const int jb = bid & 15;
    const int t  = threadIdx.x;

    // ---- Coalesced staging: 512 i-frames + 128-j chunk ----
    {
        const float* baseRp = pR + (b * NN + ib * IBL) * 9;
        const float* baseRt = tR + (b * NN + ib * IBL) * 9;
        const float* baseTp = pT + (b * NN + ib * IBL) * 3;
        const float* baseTt = tT + (b * NN + ib * IBL) * 3;
#pragma unroll
        for (int k = t; k < IBL * 9; k += BLK) { sRp[k] = baseRp[k]; sRt[k] = baseRt[k]; }
#pragma unroll
        for (int k = t; k < IBL * 3; k += BLK) { sTp[k] = baseTp[k]; sTt[k] = baseTt[k]; }

        if (t < JCH) {
            const int j = jb * JCH + t;
            const float* xp = pX + (b * NN + j) * 3;
            const float* xt = tX + (b * NN + j) * 3;
            sy[0][t] = xp[0]; sy[1][t] = xp[1]; sy[2][t] = xp[2];
            sy[3][t] = xt[0]; sy[4][t] = xt[1]; sy[5][t] = xt[2];
        }
    }
    __syncthreads();

    // ---- Two packed i-frames per thread (i0 = t, i1 = t+256) ----
    u64 P0[9], Q0[9], DT0[3], P1[9], Q1[9], DT1[3];
    build_frame(sRp + t*9,        sRt + t*9,        sTp + t*3,        sTt + t*3,        P0, Q0, DT0);
    build_frame(sRp + (t+BLK)*9,  sRt + (t+BLK)*9,  sTp + (t+BLK)*3,  sTt + (t+BLK)*3,  P1, Q1, DT1);
    const u64 EPS2 = pack2(1e-4f, 1e-4f);

    float acc0 = 0.f, acc1 = 0.f, acc2 = 0.f, acc3 = 0.f;
#pragma unroll 2
    for (int j = 0; j < JCH; j += 2) {
        // 6 warp-uniform LDS.64 feed BOTH i-chains.
        const u64 y0 = *(const u64*)&sy[0][j];
        const u64 y1 = *(const u64*)&sy[1][j];
        const u64 y2 = *(const u64*)&sy[2][j];
        const u64 y3 = *(const u64*)&sy[3][j];
        const u64 y4 = *(const u64*)&sy[4][j];
        const u64 y5 = *(const u64*)&sy[5][j];

        // i0
        u64 a0 = ffma2(P0[0], y0, ffma2(P0[1], y1, ffma2(P0[2], y2,
                 ffma2(Q0[0], y3, ffma2(Q0[1], y4, ffma2(Q0[2], y5, DT0[0]))))));
        u64 a1 = ffma2(P0[3], y0, ffma2(P0[4], y1, ffma2(P0[5], y2,
                 ffma2(Q0[3], y3, ffma2(Q0[4], y4, ffma2(Q0[5], y5, DT0[1]))))));
        u64 a2 = ffma2(P0[6], y0, ffma2(P0[7], y1, ffma2(P0[8], y2,
                 ffma2(Q0[6], y3, ffma2(Q0[7], y4, ffma2(Q0[8], y5, DT0[2]))))));
        // i1
        u64 c0 = ffma2(P1[0], y0, ffma2(P1[1], y1, ffma2(P1[2], y2,
                 ffma2(Q1[0], y3, ffma2(Q1[1], y4, ffma2(Q1[2], y5, DT1[0]))))));
        u64 c1 = ffma2(P1[3], y0, ffma2(P1[4], y1, ffma2(P1[5], y2,
                 ffma2(Q1[3], y3, ffma2(Q1[4], y4, ffma2(Q1[5], y5, DT1[1]))))));
        u64 c2 = ffma2(P1[6], y0, ffma2(P1[7], y1, ffma2(P1[8], y2,
                 ffma2(Q1[6], y3, ffma2(Q1[7], y4, ffma2(Q1[8], y5, DT1[2]))))));

        u64 sA = ffma2(a0, a0, ffma2(a1, a1, ffma2(a2, a2, EPS2)));
        u64 sC = ffma2(c0, c0, ffma2(c1, c1, ffma2(c2, c2, EPS2)));

        float aLo, aHi, cLo, cHi;
        unpack2(sA, aLo, aHi);
        unpack2(sC, cLo, cHi);
        // min(sqrt(x+eps), 10) == sqrt(min(x+eps, 100))
        acc0 += fsqrt_approx(fminf(aLo, 100.0f));
        acc1 += fsqrt_approx(fminf(aHi, 100.0f));
        acc2 += fsqrt_approx(fminf(cLo, 100.0f));
        acc3 += fsqrt_approx(fminf(cHi, 100.0f));
    }

    // ---- Deterministic reduction: warp butterfly + cross-warp ----
    float v = (acc0 + acc1) + (acc2 + acc3);
#pragma unroll
    for (int m = 16; m >= 1; m >>= 1)
        v += __shfl_xor_sync(0xffffffffu, v, m);
    if ((t & 31) == 0) swred[t >> 5] = v;
    __syncthreads();
    if (t < 32) {
        float w = (t < BLK / 32) ? swred[t] : 0.f;
#pragma unroll
        for (int m = 4; m >= 1; m >>= 1)
            w += __shfl_xor_sync(0xffffffffu, w, m);
        if (t == 0) {
            g_partials[bid] = w;
            __threadfence();
            const unsigned r = atomicAdd(&g_count, 1);
            if (r == NBLOCKS - 1) {
                // Last block: fixed-order final sum (deterministic).
#pragma unroll
                for (int bb = 0; bb < BB; bb++) {
                    float s = 0.f;
                    for (int k = 0; k < NBI * NBJ; k++)
                        s += __ldcg(&g_partials[bb * (NBI * NBJ) + k]);
                    out[bb] = s * (1.0f / (10.0f * (float)NN * (float)NN));
                }
                g_count = 0;   // reset for next graph replay
            }
        }
    }
}

extern "C" void kernel_launch(void* const* d_in, const int* in_sizes, int n_in,
                              void* d_out, int out_size) {
    const float* pR = (const float*)d_in[0];  // predicted_rotations   [B,N,3,3]
    const float* pT = (const float*)d_in[1];  // predicted_translations[B,N,3]
    const float* pX = (const float*)d_in[2];  // predicted_atom_positions
    const float* tR = (const float*)d_in[3];  // true_rotations
    const float* tT = (const float*)d_in[4];  // true_translations
    const float* tX = (const float*)d_in[5];  // true_atom_positions

    fape_fused<<<NBLOCKS, BLK>>>(pR, pT, pX, tR, tT, tX, (float*)d_out);
}

// round 9
// speedup vs baseline: 1.2338x; 1.1651x over previous
#include <cuda_runtime.h>
#include <cuda_bf16.h>
#include <cstdint>

// FAPE loss via mma.sync (HMMA bf16, register accumulators). B=4, N=2048.
// s2(i,j) = ||A_i u_j + dt_i||^2 + eps = W_i . V_j   (28-dim, padded to 32)
//   A_i = [Rp_i^T | -Rt_i^T] (3x6), u_j = [xp_j ; xt_j]
//   W_i = [diag(G), 2*offdiag(G), 2 A^T dt, |dt|^2+eps],  G = A^T A
//   V_j = [u_k^2, u_k u_l (k<l), u_k, 1]
// S2 = W @ V^T as m16n8k16 bf16 MMAs; epilogue sqrt(clamp(S2,0,100)),
// deterministic reduce. (tcgen05 is rejected by this harness's compute_103
// ptxas target; mma.sync is base PTX and still uses the tensor pipe.)

#define BB 4
#define NN 2048
#define THREADS 256
#define NWARP 8
#define ITILE 128                     // i per block (16 per warp)
#define JQ 512                        // j per block
#define JCHUNK 256                    // j staged per shared pass
#define NBLOCKS (BB * (NN/ITILE) * (NN/JQ))   // 4*16*4 = 256
#define SROW 20                       // u32 stride per V row in smem (conflict-free)

__device__ __nv_bfloat16 g_W[BB * NN * 32];
__device__ __nv_bfloat16 g_V[BB * NN * 32];
__device__ float g_partials[NBLOCKS];
__device__ unsigned int g_count = 0;

__device__ __forceinline__ float fsqrt_approx(float x) {
    float y; asm("sqrt.approx.f32 %0, %1;" : "=f"(y) : "f"(x)); return y;
}

__device__ __forceinline__ void mma16816(float d[4], const uint32_t a[4],
                                         uint32_t b0, uint32_t b1,
                                         float c0, float c1, float c2, float c3) {
    asm volatile(
        "mma.sync.aligned.m16n8k16.row.col.f32.bf16.bf16.f32 "
        "{%0,%1,%2,%3}, {%4,%5,%6,%7}, {%8,%9}, {%10,%11,%12,%13};"
        : "=f"(d[0]), "=f"(d[1]), "=f"(d[2]), "=f"(d[3])
        : "r"(a[0]), "r"(a[1]), "r"(a[2]), "r"(a[3]), "r"(b0), "r"(b1),
          "f"(c0), "f"(c1), "f"(c2), "f"(c3));
}

// ---------- Prep: build W (per i) and V (per j), bf16, K padded to 32 ----------
__global__ void fape_build(const float* __restrict__ pR, const float* __restrict__ pT,
                           const float* __restrict__ pX, const float* __restrict__ tR,
                           const float* __restrict__ tT, const float* __restrict__ tX) {
    const int gid = blockIdx.x * blockDim.x + threadIdx.x;   // 0..16383
    const int idx = gid & (BB * NN - 1);
    float v[28];
    __nv_bfloat16* dst;
    if (gid < BB * NN) {
        // V row
        const float* xp = pX + idx * 3;
        const float* xt = tX + idx * 3;
        float u[6] = {xp[0], xp[1], xp[2], xt[0], xt[1], xt[2]};
#pragma unroll
        for (int k = 0; k < 6; k++) v[k] = u[k] * u[k];
        int p = 6;
#pragma unroll
        for (int k = 0; k < 6; k++)
#pragma unroll
            for (int l = k + 1; l < 6; l++) v[p++] = u[k] * u[l];
#pragma unroll
        for (int k = 0; k < 6; k++) v[21 + k] = u[k];
        v[27] = 1.0f;
        dst = g_V + idx * 32;
    } else {
        // W row
        const float* Rp = pR + idx * 9;
        const float* Rt = tR + idx * 9;
        const float tp0 = pT[idx*3+0], tp1 = pT[idx*3+1], tp2 = pT[idx*3+2];
        const float tt0 = tT[idx*3+0], tt1 = tT[idx*3+1], tt2 = tT[idx*3+2];
        float A[3][6], dt[3];
#pragma unroll
        for (int r = 0; r < 3; r++) {
#pragma unroll
            for (int k = 0; k < 3; k++) {
                A[r][k]     =  Rp[k*3 + r];
                A[r][k + 3] = -Rt[k*3 + r];
            }
            dt[r] = (Rt[0*3+r]*tt0 + Rt[1*3+r]*tt1 + Rt[2*3+r]*tt2)
                  - (Rp[0*3+r]*tp0 + Rp[1*3+r]*tp1 + Rp[2*3+r]*tp2);
        }
#pragma unroll
        for (int k = 0; k < 6; k++)
            v[k] = A[0][k]*A[0][k] + A[1][k]*A[1][k] + A[2][k]*A[2][k];
        int p = 6;
#pragma unroll
        for (int k = 0; k < 6; k++)
#pragma unroll
            for (int l = k + 1; l < 6; l++)
                v[p++] = 2.0f * (A[0][k]*A[0][l] + A[1][k]*A[1][l] + A[2][k]*A[2][l]);
#pragma unroll
        for (int k = 0; k < 6; k++)
            v[21 + k] = 2.0f * (A[0][k]*dt[0] + A[1][k]*dt[1] + A[2][k]*dt[2]);
        v[27] = dt[0]*dt[0] + dt[1]*dt[1] + dt[2]*dt[2] + 1e-4f;
        dst = g_W + idx * 32;
    }
#pragma unroll
    for (int k = 0; k < 28; k++) dst[k] = __float2bfloat16(v[k]);
#pragma unroll
    for (int k = 28; k < 32; k++) dst[k] = __float2bfloat16(0.0f);
}

// ---------- Main: HMMA tiles + sqrt/clamp/reduce epilogue ----------
__global__ void __launch_bounds__(THREADS)
fape_mma(float* __restrict__ out) {
    __shared__ uint32_t sv[JCHUNK * SROW];    // V chunk, stride-20 rows
    __shared__ float swred[NWARP];
    __shared__ int s_last;

    const int bid = blockIdx.x;
    const int b  = bid >> 6;                  // / 64
    const int it = (bid >> 2) & 15;
    const int jq = bid & 3;
    const int t  = threadIdx.x;
    const int w  = t >> 5;
    const int lane = t & 31;
    const int gr = lane >> 2;                 // groupID
    const int tg = lane & 3;                  // thread-in-group

    // A fragments for this warp's 16 i-rows, both K halves (8 u32 from L2).
    // PTX m16n8k16 row-A mapping: a0=[gr][2tg], a1=[gr+8][2tg], a2=[gr][2tg+8], a3=[gr+8][2tg+8]
    const int i0 = it * ITILE + w * 16;
    const uint32_t* Wr = (const uint32_t*)g_W + (b * NN + i0) * 16;
    uint32_t A0[4], A1[4];
    A0[0] = Wr[gr*16 + tg];        A0[1] = Wr[(gr+8)*16 + tg];
    A0[2] = Wr[gr*16 + tg + 4];    A0[3] = Wr[(gr+8)*16 + tg + 4];
    A1[0] = Wr[gr*16 + tg + 8];    A1[1] = Wr[(gr+8)*16 + tg + 8];
    A1[2] = Wr[gr*16 + tg + 12];   A1[3] = Wr[(gr+8)*16 + tg + 12];

    float acc = 0.f;

#pragma unroll 1
    for (int ch = 0; ch < JQ / JCHUNK; ch++) {
        // Stage 256 V rows (16 u32 each) into stride-20 shared.
        const uint32_t* srcV = (const uint32_t*)g_V + (b * NN + jq * JQ + ch * JCHUNK) * 16;
        __syncthreads();
#pragma unroll
        for (int k = t; k < JCHUNK * 16; k += THREADS)
            sv[(k >> 4) * SROW + (k & 15)] = srcV[k];
        __syncthreads();

        // Each warp sweeps all 256 staged j's in steps of 8.
#pragma unroll 4
        for (int j0 = 0; j0 < JCHUNK; j0 += 8) {
            // B frags (col-major k16n8): b0=[2tg][gr-col], b1=[2tg+8][col]
            // V row-major K-contig => b0 = Vrow[j0+gr] word tg, b1 word tg+4; k-half2 +8.
            const uint32_t* vr = sv + (j0 + gr) * SROW;
            const uint32_t b0 = vr[tg];
            const uint32_t b1 = vr[tg + 4];
            const uint32_t b2 = vr[tg + 8];
            const uint32_t b3 = vr[tg + 12];

            float d[4];
            mma16816(d, A0, b0, b1, 0.f, 0.f, 0.f, 0.f);
            mma16816(d, A1, b2, b3, d[0], d[1], d[2], d[3]);

#pragma unroll
            for (int e = 0; e < 4; e++) {
                float s2 = fminf(fmaxf(d[e], 0.0f), 100.0f);  // clamp + neg guard
                acc += fsqrt_approx(s2);                      // min(sqrt,10)=sqrt(min,100)
            }
        }
    }

    // Deterministic reduction: warp butterfly, cross-warp, last-block finalize.
#pragma unroll
    for (int m = 16; m >= 1; m >>= 1)
        acc += __shfl_xor_sync(0xffffffffu, acc, m);
    if (lane == 0) swred[w] = acc;
    __syncthreads();
    if (t == 0) {
        float part = 0.f;
#pragma unroll
        for (int q = 0; q < NWARP; q++) part += swred[q];
        g_partials[bid] = part;
        __threadfence();
        const unsigned r = atomicAdd(&g_count, 1);
        s_last = (r == NBLOCKS - 1);
    }
    __syncthreads();

    if (s_last && w < BB) {
        // warp w finalizes batch w: 64 partials, fixed order per lane + butterfly.
        float s = 0.f;
#pragma unroll
        for (int q = lane; q < 64; q += 32)
            s += __ldcg(&g_partials[w * 64 + q]);
#pragma unroll
        for (int m = 16; m >= 1; m >>= 1)
            s += __shfl_xor_sync(0xffffffffu, s, m);
        if (lane == 0)
            out[w] = s * (1.0f / (10.0f * (float)NN * (float)NN));
        if (t == 0) g_count = 0;   // reset for graph replay
    }
}

extern "C" void kernel_launch(void* const* d_in, const int* in_sizes, int n_in,
                              void* d_out, int out_size) {
    const float* pR = (const float*)d_in[0];  // predicted_rotations   [B,N,3,3]
    const float* pT = (const float*)d_in[1];  // predicted_translations[B,N,3]
    const float* pX = (const float*)d_in[2];  // predicted_atom_positions
    const float* tR = (const float*)d_in[3];  // true_rotations
    const float* tT = (const float*)d_in[4];  // true_translations
    const float* tX = (const float*)d_in[5];  // true_atom_positions

    fape_build<<<(2 * BB * NN) / 256, 256>>>(pR, pT, pX, tR, tT, tX);
    fape_mma<<<NBLOCKS, THREADS>>>((float*)d_out);
}

// round 11
// speedup vs baseline: 1.9714x; 1.5978x over previous
#include <cuda_runtime.h>
#include <cuda_bf16.h>
#include <cstdint>

// FAPE loss, single fused HMMA kernel. B=4, N=2048.
// s2(i,j) = ||A_i u_j + dt_i||^2 + eps = W_i . V_j (28-dim, padded to 32)
//   A_i = [Rp_i^T | -Rt_i^T], u_j = [xp_j ; xt_j]
//   W_i = [diag(G), 2*offdiag(G), 2 A^T dt, |dt|^2+eps], G = A^T A
//   V_j = [u^2, u_k u_l (k<l), u, 1]
// W and V are built IN-BLOCK into shared (bf16), S2 = W V^T via
// mma.sync.m16n8k16, epilogue sqrt(min(|s2|,100)), deterministic reduce.
// R11 fix: B-fragment base pointer includes +tg (dropped in R10 refactor).

#define BB 4
#define NN 2048
#define THREADS 256
#define NWARP 8
#define ITILE 128
#define JQ 512
#define JCHUNK 256
#define NBLOCKS (BB * (NN/ITILE) * (NN/JQ))   // 256
#define SROW 20     // u32 stride of V rows in smem (B-frag reads conflict-free)
#define WROW 17     // u32 stride of W rows in smem

__device__ float g_partials[NBLOCKS];
__device__ unsigned int g_count = 0;

__device__ __forceinline__ float fsqrt_approx(float x) {
    float y; asm("sqrt.approx.f32 %0, %1;" : "=f"(y) : "f"(x)); return y;
}
__device__ __forceinline__ void mma16816(float d[4], const uint32_t a[4],
                                         uint32_t b0, uint32_t b1,
                                         float c0, float c1, float c2, float c3) {
    asm volatile(
        "mma.sync.aligned.m16n8k16.row.col.f32.bf16.bf16.f32 "
        "{%0,%1,%2,%3}, {%4,%5,%6,%7}, {%8,%9}, {%10,%11,%12,%13};"
        : "=f"(d[0]), "=f"(d[1]), "=f"(d[2]), "=f"(d[3])
        : "r"(a[0]), "r"(a[1]), "r"(a[2]), "r"(a[3]), "r"(b0), "r"(b1),
          "f"(c0), "f"(c1), "f"(c2), "f"(c3));
}
__device__ __forceinline__ uint32_t pack_bf2(float lo, float hi) {
    __nv_bfloat162 h = __floats2bfloat162_rn(lo, hi);   // x=lo, y=hi
    return *(uint32_t*)&h;
}

__global__ void __launch_bounds__(THREADS)
fape_fused(const float* __restrict__ pR, const float* __restrict__ pT,
           const float* __restrict__ pX, const float* __restrict__ tR,
           const float* __restrict__ tT, const float* __restrict__ tX,
           float* __restrict__ out) {
    __shared__ float    sIn[3072];               // 12 KB staging (reused)
    __shared__ uint32_t sw[ITILE * WROW];        // W rows, bf16x2 words
    __shared__ uint32_t sv[JCHUNK * SROW];       // V rows, bf16x2 words
    __shared__ float swred[NWARP];
    __shared__ int s_last;

    const int bid = blockIdx.x;
    const int b  = bid >> 6;
    const int it = (bid >> 2) & 15;
    const int jq = bid & 3;
    const int t  = threadIdx.x;
    const int w  = t >> 5;
    const int lane = t & 31;
    const int gr = lane >> 2;
    const int tg = lane & 3;

    // ---- Phase 1: stage W inputs coalesced, build 128 W rows into sw ----
    {
        const int i0 = b * NN + it * ITILE;
        const float* baseRp = pR + i0 * 9;
        const float* baseRt = tR + i0 * 9;
        const float* baseTp = pT + i0 * 3;
        const float* baseTt = tT + i0 * 3;
#pragma unroll
        for (int k = t; k < ITILE * 9; k += THREADS) {
            sIn[k] = baseRp[k];            // [0:1152) Rp
            sIn[1152 + k] = baseRt[k];     // [1152:2304) Rt
        }
#pragma unroll
        for (int k = t; k < ITILE * 3; k += THREADS) {
            sIn[2304 + k] = baseTp[k];     // [2304:2688) tp
            sIn[2688 + k] = baseTt[k];     // [2688:3072) tt
        }
    }
    __syncthreads();

    if (t < ITILE) {
        const float* Rp = sIn + t * 9;
        const float* Rt = sIn + 1152 + t * 9;
        const float tp0 = sIn[2304 + t*3], tp1 = sIn[2304 + t*3+1], tp2 = sIn[2304 + t*3+2];
        const float tt0 = sIn[2688 + t*3], tt1 = sIn[2688 + t*3+1], tt2 = sIn[2688 + t*3+2];
        float A[3][6], dt[3], v[28];
#pragma unroll
        for (int r = 0; r < 3; r++) {
#pragma unroll
            for (int k = 0; k < 3; k++) {
                A[r][k]     =  Rp[k*3 + r];
                A[r][k + 3] = -Rt[k*3 + r];
            }
            dt[r] = (Rt[0*3+r]*tt0 + Rt[1*3+r]*tt1 + Rt[2*3+r]*tt2)
                  - (Rp[0*3+r]*tp0 + Rp[1*3+r]*tp1 + Rp[2*3+r]*tp2);
        }
#pragma unroll
        for (int k = 0; k < 6; k++)
            v[k] = A[0][k]*A[0][k] + A[1][k]*A[1][k] + A[2][k]*A[2][k];
        int p = 6;
#pragma unroll
        for (int k = 0; k < 6; k++)
#pragma unroll
            for (int l = k + 1; l < 6; l++)
                v[p++] = 2.0f * (A[0][k]*A[0][l] + A[1][k]*A[1][l] + A[2][k]*A[2][l]);
#pragma unroll
        for (int k = 0; k < 6; k++)
            v[21 + k] = 2.0f * (A[0][k]*dt[0] + A[1][k]*dt[1] + A[2][k]*dt[2]);
        v[27] = dt[0]*dt[0] + dt[1]*dt[1] + dt[2]*dt[2] + 1e-4f;

        uint32_t* dst = sw + t * WROW;
#pragma unroll
        for (int c = 0; c < 14; c++) dst[c] = pack_bf2(v[2*c], v[2*c+1]);
        dst[14] = 0u; dst[15] = 0u;
    }
    __syncthreads();

    // ---- A fragments (warp w owns i-rows w*16 .. w*16+15), both K halves ----
    uint32_t A0[4], A1[4];
    {
        const uint32_t* r0 = sw + (w * 16 + gr) * WROW;
        const uint32_t* r8 = sw + (w * 16 + gr + 8) * WROW;
        A0[0] = r0[tg];      A0[1] = r8[tg];
        A0[2] = r0[tg + 4];  A0[3] = r8[tg + 4];
        A1[0] = r0[tg + 8];  A1[1] = r8[tg + 8];
        A1[2] = r0[tg + 12]; A1[3] = r8[tg + 12];
    }

    float acc = 0.f;

#pragma unroll 1
    for (int ch = 0; ch < JQ / JCHUNK; ch++) {
        // ---- Phase 2: stage xp/xt chunk coalesced, build 256 V rows ----
        const int j0g = b * NN + jq * JQ + ch * JCHUNK;
        __syncthreads();
#pragma unroll
        for (int k = t; k < JCHUNK * 3; k += THREADS) {
            sIn[k] = pX[j0g * 3 + k];                 // [0:768) xp
            sIn[768 + k] = tX[j0g * 3 + k];           // [768:1536) xt
        }
        __syncthreads();
        {
            const float* xp = sIn + t * 3;
            const float* xt = sIn + 768 + t * 3;
            float u[6] = {xp[0], xp[1], xp[2], xt[0], xt[1], xt[2]};
            float v[28];
#pragma unroll
            for (int k = 0; k < 6; k++) v[k] = u[k] * u[k];
            int p = 6;
#pragma unroll
            for (int k = 0; k < 6; k++)
#pragma unroll
                for (int l = k + 1; l < 6; l++) v[p++] = u[k] * u[l];
#pragma unroll
            for (int k = 0; k < 6; k++) v[21 + k] = u[k];
            v[27] = 1.0f;
            uint32_t* dst = sv + t * SROW;
#pragma unroll
            for (int c = 0; c < 14; c++) dst[c] = pack_bf2(v[2*c], v[2*c+1]);
            dst[14] = 0u; dst[15] = 0u;
        }
        __syncthreads();

        // ---- Phase 3: MMA sweep over the 256 staged j's ----
        // B frag for rows j0+gr: thread-in-group tg reads K-words tg, tg+4, tg+8, tg+12.
        const uint32_t* vr = sv + gr * SROW + tg;
#pragma unroll 4
        for (int j0 = 0; j0 < JCHUNK; j0 += 8) {
            const uint32_t b0 = vr[0];
            const uint32_t b1 = vr[4];
            const uint32_t b2 = vr[8];
            const uint32_t b3 = vr[12];
            vr += 8 * SROW;

            float d[4];
            mma16816(d, A0, b0, b1, 0.f, 0.f, 0.f, 0.f);
            mma16816(d, A1, b2, b3, d[0], d[1], d[2], d[3]);

#pragma unroll
            for (int e = 0; e < 4; e++)
                acc += fsqrt_approx(fminf(fabsf(d[e]), 100.0f));
        }
    }

    // ---- Deterministic reduction + last-block finalize ----
#pragma unroll
    for (int m = 16; m >= 1; m >>= 1)
        acc += __shfl_xor_sync(0xffffffffu, acc, m);
    if (lane == 0) swred[w] = acc;
    __syncthreads();
    if (t == 0) {
        float part = 0.f;
#pragma unroll
        for (int q = 0; q < NWARP; q++) part += swred[q];
        g_partials[bid] = part;
        __threadfence();
        const unsigned r = atomicAdd(&g_count, 1);
        s_last = (r == NBLOCKS - 1);
    }
    __syncthreads();

    if (s_last && w < BB) {
        float s = 0.f;
#pragma unroll
        for (int q = lane; q < 64; q += 32)
            s += __ldcg(&g_partials[w * 64 + q]);
#pragma unroll
        for (int m = 16; m >= 1; m >>= 1)
            s += __shfl_xor_sync(0xffffffffu, s, m);
        if (lane == 0)
            out[w] = s * (1.0f / (10.0f * (float)NN * (float)NN));
        if (t == 0) g_count = 0;   // reset for graph replay
    }
}

extern "C" void kernel_launch(void* const* d_in, const int* in_sizes, int n_in,
                              void* d_out, int out_size) {
    const float* pR = (const float*)d_in[0];  // predicted_rotations   [B,N,3,3]
    const float* pT = (const float*)d_in[1];  // predicted_translations[B,N,3]
    const float* pX = (const float*)d_in[2];  // predicted_atom_positions
    const float* tR = (const float*)d_in[3];  // true_rotations
    const float* tT = (const float*)d_in[4];  // true_translations
    const float* tX = (const float*)d_in[5];  // true_atom_positions

    fape_fused<<<NBLOCKS, THREADS>>>(pR, pT, pX, tR, tT, tX, (float*)d_out);
}